// round 4
// baseline (speedup 1.0000x reference)
#include <cuda_runtime.h>
#include <cuda_bf16.h>
#include <math.h>

// Problem constants
#define S   1024
#define E   512
#define H   512
#define G3  1536      // 3*H
#define D1  1024
#define R4  2048      // 4*H
#define VOC 50257

#define NDIR 4
#define BPD  37       // blocks per direction (4*37 = 148 blocks, 1 per SM)
#define RPB  14       // max h-rows per block (37*14 = 518 >= 512)
#define NTH  256

// ---------------- device scratch (no allocations allowed) ----------------
__device__ float g_x[S * E];                          // embedded sequence [S][E]
__device__ float g_gi[NDIR * S * G3];                 // input-side gates
__device__ unsigned long long g_hb[NDIR * 2 * H];     // tagged hidden: (fbits<<32)|tag
__device__ float g_hfinal[NDIR * H];                  // rep = [ctx_f, ctx_b, qry_f, qry_b]
__device__ float g_h1[D1];                            // dense1 output

// ---------------- sync primitives ----------------
__device__ __forceinline__ unsigned long long ld_acq64(const unsigned long long* p) {
    unsigned long long v;
    asm volatile("ld.acquire.gpu.global.b64 %0, [%1];" : "=l"(v) : "l"(p) : "memory");
    return v;
}
__device__ __forceinline__ void st_rel64(unsigned long long* p, unsigned long long v) {
    asm volatile("st.release.gpu.global.b64 [%0], %1;" :: "l"(p), "l"(v) : "memory");
}

// ---------------- fast activations ----------------
__device__ __forceinline__ float fsigmoid(float x) {
    return 1.f / (1.f + __expf(-x));
}
__device__ __forceinline__ float ftanh(float x) {
    return 2.f / (1.f + __expf(-2.f * x)) - 1.f;
}

// ---------------- reset tags ----------------
__global__ void k_reset() {
    int i = blockIdx.x * blockDim.x + threadIdx.x;
    if (i < NDIR * 2 * H) g_hb[i] = 0ull;
}

// ---------------- embedding gather (with int32/int64 sniffing) ----------------
__global__ void k_gather(const void* __restrict__ sent, const float* __restrict__ emb) {
    __shared__ int is64;
    if (threadIdx.x == 0) {
        const long long* p = (const long long*)sent;
        bool ok = true;
        #pragma unroll
        for (int i = 0; i < 4; i++) {
            long long v = p[i];
            if (v < 0 || v >= VOC) ok = false;
        }
        is64 = ok ? 1 : 0;
    }
    __syncthreads();
    int t = blockIdx.x;
    long long idx = is64 ? ((const long long*)sent)[t]
                         : (long long)((const int*)sent)[t];
    const float4* src = (const float4*)(emb + (size_t)idx * E);
    float4* dst = (float4*)(g_x + (size_t)t * E);
    for (int k = threadIdx.x; k < E / 4; k += blockDim.x) dst[k] = src[k];
}

// ---------------- gi GEMM: gi[d][t][r] = sum_k x[t][k]*Wih[d][r][k] + bih[d][r] ----
struct GemmArgs { const float* Wih[4]; const float* bih[4]; };

#define BM 128
#define BN 128
#define BK 16
__global__ void __launch_bounds__(256) k_gemm_gi(GemmArgs a) {
    int d = blockIdx.z;
    const float* __restrict__ Wih = a.Wih[d];
    const float* __restrict__ bih = a.bih[d];
    float* out = g_gi + (size_t)d * S * G3;

    __shared__ float sA[BK][BM + 4];   // x:   [k][t]
    __shared__ float sB[BK][BN + 4];   // Wih: [k][r]

    int t0 = blockIdx.x * BM;
    int r0 = blockIdx.y * BN;
    int tx = threadIdx.x & 15;         // t-direction (8 rows each)
    int ty = threadIdx.x >> 4;         // r-direction (8 cols each)

    float acc[8][8];
    #pragma unroll
    for (int i = 0; i < 8; i++)
        #pragma unroll
        for (int j = 0; j < 8; j++) acc[i][j] = 0.f;

    int lrow = threadIdx.x >> 2;        // 0..63
    int lk   = (threadIdx.x & 3) * 4;   // 0,4,8,12

    for (int k0 = 0; k0 < E; k0 += BK) {
        #pragma unroll
        for (int i = 0; i < 2; i++) {
            int row = lrow + i * 64;
            float4 va = *(const float4*)(g_x + (size_t)(t0 + row) * E + k0 + lk);
            float4 vb = *(const float4*)(Wih + (size_t)(r0 + row) * E + k0 + lk);
            sA[lk + 0][row] = va.x; sA[lk + 1][row] = va.y;
            sA[lk + 2][row] = va.z; sA[lk + 3][row] = va.w;
            sB[lk + 0][row] = vb.x; sB[lk + 1][row] = vb.y;
            sB[lk + 2][row] = vb.z; sB[lk + 3][row] = vb.w;
        }
        __syncthreads();
        #pragma unroll
        for (int kk = 0; kk < BK; kk++) {
            float ar[8], br[8];
            *(float4*)(ar + 0) = *(const float4*)&sA[kk][tx * 8 + 0];
            *(float4*)(ar + 4) = *(const float4*)&sA[kk][tx * 8 + 4];
            *(float4*)(br + 0) = *(const float4*)&sB[kk][ty * 8 + 0];
            *(float4*)(br + 4) = *(const float4*)&sB[kk][ty * 8 + 4];
            #pragma unroll
            for (int i = 0; i < 8; i++)
                #pragma unroll
                for (int j = 0; j < 8; j++) acc[i][j] = fmaf(ar[i], br[j], acc[i][j]);
        }
        __syncthreads();
    }
    #pragma unroll
    for (int i = 0; i < 8; i++) {
        int t = t0 + tx * 8 + i;
        int r = r0 + ty * 8;
        #pragma unroll
        for (int j4 = 0; j4 < 2; j4++) {
            float4 v;
            v.x = acc[i][j4 * 4 + 0] + __ldg(bih + r + j4 * 4 + 0);
            v.y = acc[i][j4 * 4 + 1] + __ldg(bih + r + j4 * 4 + 1);
            v.z = acc[i][j4 * 4 + 2] + __ldg(bih + r + j4 * 4 + 2);
            v.w = acc[i][j4 * 4 + 3] + __ldg(bih + r + j4 * 4 + 3);
            *(float4*)(out + (size_t)t * G3 + r + j4 * 4) = v;
        }
    }
}

// ---------------- recurrent scan kernel ----------------
struct ScanArgs { const float* Whh[4]; const float* bhh[4]; };

__global__ void __launch_bounds__(NTH, 1) k_scan(ScanArgs a) {
    extern __shared__ float sw[];                    // [RPB*3*H] weights
    float* sgate = sw + RPB * 3 * H;                 // [2][64] gate partials (dbl-buffered)

    const int blk   = blockIdx.x;
    const int d     = blk / BPD;
    const int b     = blk % BPD;
    const int hbase = b * RPB;
    const int nrows = min(RPB, H - hbase);
    const int nrg   = nrows * 3;

    const float* __restrict__ Whh = a.Whh[d];
    const float* __restrict__ bhh = a.bhh[d];
    const float* __restrict__ gi  = g_gi + (size_t)d * S * G3;
    unsigned long long* hb_base = g_hb + (size_t)d * 2 * H;

    const int tid  = threadIdx.x;
    const int lane = tid & 31;
    const int w    = tid >> 5;
    const bool back = (d & 1);

    // Stage Whh slice into shared: sw[(j*3+g)*H + k] = Whh[(g*H + hbase + j)*H + k]
    for (int x = tid; x < nrg * (H / 4); x += NTH) {
        int rg = x / (H / 4);
        int k4 = x - rg * (H / 4);
        int j = rg / 3, g = rg - j * 3;
        const float4 v = ((const float4*)(Whh + (size_t)(g * H + hbase + j) * H))[k4];
        ((float4*)(sw + (size_t)rg * H))[k4] = v;
    }
    // per-row biases + running hidden value (owned by thread j < nrows)
    float br = 0.f, bz = 0.f, bn = 0.f, hreg = 0.f;
    if (tid < nrows) {
        int i = hbase + tid;
        br = bhh[i]; bz = bhh[H + i]; bn = bhh[2 * H + i];
    }
    __syncthreads();

    for (int t = 0; t < S; ++t) {
        const int te = back ? (S - 1 - t) : t;

        // prefetch input-side gates (independent of h)
        float gr_ = 0.f, gz_ = 0.f, gn_ = 0.f;
        if (tid < nrows) {
            const float* grow = gi + (size_t)te * G3 + hbase + tid;
            gr_ = __ldg(grow);
            gz_ = __ldg(grow + H);
            gn_ = __ldg(grow + 2 * H);
        }

        // load tagged hidden state of step t-1 (each warp loads full h)
        float hk[16];
        if (t == 0) {
            #pragma unroll
            for (int kk = 0; kk < 16; kk++) hk[kk] = 0.f;
        } else {
            const unsigned long long* hb = hb_base + (size_t)((t - 1) & 1) * H;
            const unsigned tag = (unsigned)t;
            // spin on element 0 of this lane
            unsigned long long v0 = ld_acq64(hb + lane);
            while ((unsigned)v0 != tag) v0 = ld_acq64(hb + lane);
            hk[0] = __uint_as_float((unsigned)(v0 >> 32));
            // batch-load remaining 15 with pending-mask retry
            unsigned long long vv[16];
            unsigned pend = 0xFFFEu;
            while (pend) {
                #pragma unroll
                for (int kk = 1; kk < 16; kk++)
                    if (pend & (1u << kk)) vv[kk] = ld_acq64(hb + lane + 32 * kk);
                #pragma unroll
                for (int kk = 1; kk < 16; kk++)
                    if ((pend & (1u << kk)) && (unsigned)vv[kk] == tag) {
                        hk[kk] = __uint_as_float((unsigned)(vv[kk] >> 32));
                        pend &= ~(1u << kk);
                    }
            }
        }

        // gh partials: warp w handles row-gates w, w+8, ...
        float* sg = sgate + (t & 1) * 64;
        for (int rg = w; rg < nrg; rg += 8) {
            const float* wr = sw + (size_t)rg * H;
            float acc = 0.f;
            #pragma unroll
            for (int kk = 0; kk < 16; kk++)
                acc = fmaf(wr[lane + 32 * kk], hk[kk], acc);
            #pragma unroll
            for (int off = 16; off > 0; off >>= 1)
                acc += __shfl_xor_sync(0xFFFFFFFFu, acc, off);
            if (lane == 0) sg[rg] = acc;
        }
        __syncthreads();   // one barrier per step: partials -> gate math

        // gate math + publish (thread j owns h row hbase+j)
        if (tid < nrows) {
            float ghr = sg[tid * 3 + 0] + br;
            float ghz = sg[tid * 3 + 1] + bz;
            float ghn = sg[tid * 3 + 2] + bn;
            float r = fsigmoid(gr_ + ghr);
            float z = fsigmoid(gz_ + ghz);
            float n = ftanh(gn_ + r * ghn);
            float hnew = (1.f - z) * n + z * hreg;
            hreg = hnew;
            unsigned long long packed =
                ((unsigned long long)__float_as_uint(hnew) << 32) | (unsigned)(t + 1);
            st_rel64(hb_base + (size_t)(t & 1) * H + hbase + tid, packed);
            if (t == S - 1) g_hfinal[d * H + hbase + tid] = hnew;
        }
        // no trailing barrier: other warps self-block on next step's tag spin
    }
}

// ---------------- dense1: h1 = relu(d1_w @ rep + d1_b) ----------------
__global__ void __launch_bounds__(256) k_dense1(const float* __restrict__ d1w,
                                                const float* __restrict__ d1b) {
    int warp = threadIdx.x >> 5, lane = threadIdx.x & 31;
    int row = blockIdx.x * 8 + warp;          // grid 128 -> 1024 rows
    const float* wr = d1w + (size_t)row * R4;
    float acc = 0.f;
    #pragma unroll 8
    for (int k = lane; k < R4; k += 32)
        acc = fmaf(wr[k], g_hfinal[k], acc);
    #pragma unroll
    for (int off = 16; off > 0; off >>= 1)
        acc += __shfl_xor_sync(0xFFFFFFFFu, acc, off);
    if (lane == 0) g_h1[row] = fmaxf(acc + d1b[row], 0.f);
}

// ---------------- dense2: out = sigmoid(d2_w . h1 + d2_b) ----------------
__global__ void __launch_bounds__(1024) k_dense2(const float* __restrict__ d2w,
                                                 const float* __restrict__ d2b,
                                                 float* __restrict__ out) {
    __shared__ float red[32];
    int tid = threadIdx.x, lane = tid & 31;
    float v = g_h1[tid] * d2w[tid];
    #pragma unroll
    for (int off = 16; off > 0; off >>= 1)
        v += __shfl_xor_sync(0xFFFFFFFFu, v, off);
    if (lane == 0) red[tid >> 5] = v;
    __syncthreads();
    if (tid < 32) {
        float s = red[tid];
        #pragma unroll
        for (int off = 16; off > 0; off >>= 1)
            s += __shfl_xor_sync(0xFFFFFFFFu, s, off);
        if (tid == 0) out[0] = 1.f / (1.f + expf(-(s + d2b[0])));
    }
}

// ---------------- launch ----------------
extern "C" void kernel_launch(void* const* d_in, const int* in_sizes, int n_in,
                              void* d_out, int out_size) {
    const void*  sent = d_in[0];
    const float* emb  = (const float*)d_in[1];

    GemmArgs ga; ScanArgs sa;
    for (int d = 0; d < 4; d++) {
        ga.Wih[d] = (const float*)d_in[2 + 4 * d + 0];
        sa.Whh[d] = (const float*)d_in[2 + 4 * d + 1];
        ga.bih[d] = (const float*)d_in[2 + 4 * d + 2];
        sa.bhh[d] = (const float*)d_in[2 + 4 * d + 3];
    }
    const float* d1w = (const float*)d_in[18];
    const float* d1b = (const float*)d_in[19];
    const float* d2w = (const float*)d_in[20];
    const float* d2b = (const float*)d_in[21];
    float* out = (float*)d_out;

    static const size_t scan_smem = (size_t)(RPB * 3 * H + 128) * sizeof(float);
    cudaFuncSetAttribute(k_scan, cudaFuncAttributeMaxDynamicSharedMemorySize,
                         (int)scan_smem);

    k_reset<<<(NDIR * 2 * H + 255) / 256, 256>>>();
    k_gather<<<S, 128>>>(sent, emb);
    k_gemm_gi<<<dim3(S / BM, G3 / BN, NDIR), 256>>>(ga);
    k_scan<<<NDIR * BPD, NTH, scan_smem>>>(sa);
    k_dense1<<<D1 / 8, 256>>>(d1w, d1b);
    k_dense2<<<1, 1024>>>(d2w, d2b, out);
}

// round 6
// speedup vs baseline: 1.2411x; 1.2411x over previous
#include <cuda_runtime.h>
#include <cuda_bf16.h>
#include <math.h>

// Problem constants
#define S   1024
#define E   512
#define H   512
#define G3  1536      // 3*H
#define D1  1024
#define R4  2048      // 4*H
#define VOC 50257

#define NDIR 4
#define BPD  32       // blocks per direction (4*32 = 128 blocks, 1 per SM)
#define RPB  16       // h-rows per block (32*16 = 512)
#define NTH  256      // 8 warps, each owns 2 h-rows (w and w+8)

// ---------------- device scratch (no allocations allowed) ----------------
__device__ float g_x[S * E];                          // embedded sequence [S][E]
__device__ float g_gi[NDIR * S * G3];                 // input-side gates
__device__ unsigned long long g_hb[NDIR * 2 * H];     // tagged hidden: (fbits<<32)|tag
__device__ float g_hfinal[NDIR * H];                  // rep = [ctx_f, ctx_b, qry_f, qry_b]
__device__ float g_h1[D1];                            // dense1 output

// ---------------- sync primitives ----------------
__device__ __forceinline__ unsigned long long ld_acq64(const unsigned long long* p) {
    unsigned long long v;
    asm volatile("ld.acquire.gpu.global.b64 %0, [%1];" : "=l"(v) : "l"(p) : "memory");
    return v;
}
__device__ __forceinline__ void st_rel64(unsigned long long* p, unsigned long long v) {
    asm volatile("st.release.gpu.global.b64 [%0], %1;" :: "l"(p), "l"(v) : "memory");
}

// ---------------- fast activations ----------------
__device__ __forceinline__ float fsigmoid(float x) {
    return 1.f / (1.f + __expf(-x));
}
__device__ __forceinline__ float ftanh(float x) {
    return 2.f / (1.f + __expf(-2.f * x)) - 1.f;
}

// ---------------- reset tags ----------------
__global__ void k_reset() {
    int i = blockIdx.x * blockDim.x + threadIdx.x;
    if (i < NDIR * 2 * H) g_hb[i] = 0ull;
}

// ---------------- embedding gather (with int32/int64 sniffing) ----------------
__global__ void k_gather(const void* __restrict__ sent, const float* __restrict__ emb) {
    __shared__ int is64;
    if (threadIdx.x == 0) {
        const long long* p = (const long long*)sent;
        bool ok = true;
        #pragma unroll
        for (int i = 0; i < 4; i++) {
            long long v = p[i];
            if (v < 0 || v >= VOC) ok = false;
        }
        is64 = ok ? 1 : 0;
    }
    __syncthreads();
    int t = blockIdx.x;
    long long idx = is64 ? ((const long long*)sent)[t]
                         : (long long)((const int*)sent)[t];
    const float4* src = (const float4*)(emb + (size_t)idx * E);
    float4* dst = (float4*)(g_x + (size_t)t * E);
    for (int k = threadIdx.x; k < E / 4; k += blockDim.x) dst[k] = src[k];
}

// ---------------- gi GEMM: gi[d][t][r] = sum_k x[t][k]*Wih[d][r][k] + bih[d][r] ----
struct GemmArgs { const float* Wih[4]; const float* bih[4]; };

#define BM 128
#define BN 128
#define BK 16
__global__ void __launch_bounds__(256) k_gemm_gi(GemmArgs a) {
    int d = blockIdx.z;
    const float* __restrict__ Wih = a.Wih[d];
    const float* __restrict__ bih = a.bih[d];
    float* out = g_gi + (size_t)d * S * G3;

    __shared__ float sA[BK][BM + 4];   // x:   [k][t]
    __shared__ float sB[BK][BN + 4];   // Wih: [k][r]

    int t0 = blockIdx.x * BM;
    int r0 = blockIdx.y * BN;
    int tx = threadIdx.x & 15;         // t-direction (8 rows each)
    int ty = threadIdx.x >> 4;         // r-direction (8 cols each)

    float acc[8][8];
    #pragma unroll
    for (int i = 0; i < 8; i++)
        #pragma unroll
        for (int j = 0; j < 8; j++) acc[i][j] = 0.f;

    int lrow = threadIdx.x >> 2;        // 0..63
    int lk   = (threadIdx.x & 3) * 4;   // 0,4,8,12

    for (int k0 = 0; k0 < E; k0 += BK) {
        #pragma unroll
        for (int i = 0; i < 2; i++) {
            int row = lrow + i * 64;
            float4 va = *(const float4*)(g_x + (size_t)(t0 + row) * E + k0 + lk);
            float4 vb = *(const float4*)(Wih + (size_t)(r0 + row) * E + k0 + lk);
            sA[lk + 0][row] = va.x; sA[lk + 1][row] = va.y;
            sA[lk + 2][row] = va.z; sA[lk + 3][row] = va.w;
            sB[lk + 0][row] = vb.x; sB[lk + 1][row] = vb.y;
            sB[lk + 2][row] = vb.z; sB[lk + 3][row] = vb.w;
        }
        __syncthreads();
        #pragma unroll
        for (int kk = 0; kk < BK; kk++) {
            float ar[8], br[8];
            *(float4*)(ar + 0) = *(const float4*)&sA[kk][tx * 8 + 0];
            *(float4*)(ar + 4) = *(const float4*)&sA[kk][tx * 8 + 4];
            *(float4*)(br + 0) = *(const float4*)&sB[kk][ty * 8 + 0];
            *(float4*)(br + 4) = *(const float4*)&sB[kk][ty * 8 + 4];
            #pragma unroll
            for (int i = 0; i < 8; i++)
                #pragma unroll
                for (int j = 0; j < 8; j++) acc[i][j] = fmaf(ar[i], br[j], acc[i][j]);
        }
        __syncthreads();
    }
    #pragma unroll
    for (int i = 0; i < 8; i++) {
        int t = t0 + tx * 8 + i;
        int r = r0 + ty * 8;
        #pragma unroll
        for (int j4 = 0; j4 < 2; j4++) {
            float4 v;
            v.x = acc[i][j4 * 4 + 0] + __ldg(bih + r + j4 * 4 + 0);
            v.y = acc[i][j4 * 4 + 1] + __ldg(bih + r + j4 * 4 + 1);
            v.z = acc[i][j4 * 4 + 2] + __ldg(bih + r + j4 * 4 + 2);
            v.w = acc[i][j4 * 4 + 3] + __ldg(bih + r + j4 * 4 + 3);
            *(float4*)(out + (size_t)t * G3 + r + j4 * 4) = v;
        }
    }
}

// ---------------- recurrent scan kernel ----------------
// Block layout: 8 warps; warp w owns local h-rows {w, w+8} and ALL THREE gate
// rows for each. One __syncthreads per step. Warp 0 additionally polls the
// tagged global h of step t-1 into a double-buffered smem array.
struct ScanArgs { const float* Whh[4]; const float* bhh[4]; };

__global__ void __launch_bounds__(NTH, 1) k_scan(ScanArgs a) {
    extern __shared__ float sw[];            // [RPB*3*H] weights (96 KB)
    float* sh = sw + RPB * 3 * H;            // [2][H] hidden state (dbl-buffered)

    const int blk   = blockIdx.x;
    const int d     = blk / BPD;
    const int b     = blk % BPD;
    const int hbase = b * RPB;

    const float* __restrict__ Whh = a.Whh[d];
    const float* __restrict__ bhh = a.bhh[d];
    const float* __restrict__ gi  = g_gi + (size_t)d * S * G3;
    unsigned long long* hb_base = g_hb + (size_t)d * 2 * H;

    const int tid  = threadIdx.x;
    const int lane = tid & 31;
    const int w    = tid >> 5;
    const bool back = (d & 1);

    // Stage Whh slice: sw[(j*3+g)*H + k] = Whh[(g*H + hbase + j)*H + k]
    for (int x = tid; x < RPB * 3 * (H / 4); x += NTH) {
        int rg = x / (H / 4);
        int k4 = x - rg * (H / 4);
        int j = rg / 3, g = rg - j * 3;
        const float4 v = ((const float4*)(Whh + (size_t)(g * H + hbase + j) * H))[k4];
        ((float4*)(sw + (size_t)rg * H))[k4] = v;
    }

    // Lane 0/1 of warp w own rows (hbase + w) and (hbase + w + 8)
    const int myrow = hbase + w + lane * 8;          // valid for lane < 2
    float br = 0.f, bz = 0.f, bn = 0.f, hreg = 0.f;
    if (lane < 2) {
        br = bhh[myrow]; bz = bhh[H + myrow]; bn = bhh[2 * H + myrow];
    }
    __syncthreads();

    for (int t = 0; t < S; ++t) {
        const int te = back ? (S - 1 - t) : t;

        // prefetch input-side gates (independent of h)
        float gr_ = 0.f, gz_ = 0.f, gn_ = 0.f;
        if (lane < 2) {
            const float* grow = gi + (size_t)te * G3 + myrow;
            gr_ = __ldg(grow);
            gz_ = __ldg(grow + H);
            gn_ = __ldg(grow + 2 * H);
        }

        float* shb = sh + (t & 1) * H;

        // warp 0: poll tagged global h of step t-1 into smem
        if (t > 0 && w == 0) {
            const unsigned long long* hb = hb_base + (size_t)((t - 1) & 1) * H;
            const unsigned tag = (unsigned)t;
            unsigned long long vv[16];
            unsigned pend = 0xFFFFu;
            while (pend) {
                #pragma unroll
                for (int kk = 0; kk < 16; kk++)
                    if (pend & (1u << kk)) vv[kk] = ld_acq64(hb + lane + 32 * kk);
                #pragma unroll
                for (int kk = 0; kk < 16; kk++)
                    if ((pend & (1u << kk)) && (unsigned)vv[kk] == tag) {
                        shb[lane + 32 * kk] = __uint_as_float((unsigned)(vv[kk] >> 32));
                        pend &= ~(1u << kk);
                    }
            }
        }
        __syncthreads();   // the only barrier per step

        // load h into registers (float4-granular)
        float4 h4[4];
        if (t == 0) {
            #pragma unroll
            for (int c = 0; c < 4; c++) h4[c] = make_float4(0.f, 0.f, 0.f, 0.f);
        } else {
            const float4* shb4 = (const float4*)shb;
            #pragma unroll
            for (int c = 0; c < 4; c++) h4[c] = shb4[lane + 32 * c];
        }

        // 6 dot products: rows {w, w+8} x gates {r,z,n}
        float dots[6];
        #pragma unroll
        for (int jj = 0; jj < 2; jj++) {
            int j = w + jj * 8;
            #pragma unroll
            for (int g = 0; g < 3; g++) {
                const float4* wr = (const float4*)(sw + (size_t)(j * 3 + g) * H);
                float acc = 0.f;
                #pragma unroll
                for (int c = 0; c < 4; c++) {
                    float4 wv = wr[lane + 32 * c];
                    acc = fmaf(wv.x, h4[c].x, acc);
                    acc = fmaf(wv.y, h4[c].y, acc);
                    acc = fmaf(wv.z, h4[c].z, acc);
                    acc = fmaf(wv.w, h4[c].w, acc);
                }
                dots[jj * 3 + g] = acc;
            }
        }
        // butterfly reduce all 6 (results in every lane)
        #pragma unroll
        for (int off = 16; off > 0; off >>= 1) {
            #pragma unroll
            for (int i = 0; i < 6; i++)
                dots[i] += __shfl_xor_sync(0xFFFFFFFFu, dots[i], off);
        }

        // gate math + tagged publish (lanes 0,1 own the two rows)
        if (lane < 2) {
            float ghr = dots[lane * 3 + 0] + br;
            float ghz = dots[lane * 3 + 1] + bz;
            float ghn = dots[lane * 3 + 2] + bn;
            float r = fsigmoid(gr_ + ghr);
            float z = fsigmoid(gz_ + ghz);
            float n = ftanh(gn_ + r * ghn);
            float hnew = (1.f - z) * n + z * hreg;
            hreg = hnew;
            unsigned long long packed =
                ((unsigned long long)__float_as_uint(hnew) << 32) | (unsigned)(t + 1);
            st_rel64(hb_base + (size_t)(t & 1) * H + myrow, packed);
            if (t == S - 1) g_hfinal[d * H + myrow] = hnew;
        }
        // no trailing barrier: next step's poll + syncthreads provide ordering
    }
}

// ---------------- dense1: h1 = relu(d1_w @ rep + d1_b) ----------------
__global__ void __launch_bounds__(256) k_dense1(const float* __restrict__ d1w,
                                                const float* __restrict__ d1b) {
    int warp = threadIdx.x >> 5, lane = threadIdx.x & 31;
    int row = blockIdx.x * 8 + warp;          // grid 128 -> 1024 rows
    const float* wr = d1w + (size_t)row * R4;
    float acc = 0.f;
    #pragma unroll 8
    for (int k = lane; k < R4; k += 32)
        acc = fmaf(wr[k], g_hfinal[k], acc);
    #pragma unroll
    for (int off = 16; off > 0; off >>= 1)
        acc += __shfl_xor_sync(0xFFFFFFFFu, acc, off);
    if (lane == 0) g_h1[row] = fmaxf(acc + d1b[row], 0.f);
}

// ---------------- dense2: out = sigmoid(d2_w . h1 + d2_b) ----------------
__global__ void __launch_bounds__(1024) k_dense2(const float* __restrict__ d2w,
                                                 const float* __restrict__ d2b,
                                                 float* __restrict__ out) {
    __shared__ float red[32];
    int tid = threadIdx.x, lane = tid & 31;
    float v = g_h1[tid] * d2w[tid];
    #pragma unroll
    for (int off = 16; off > 0; off >>= 1)
        v += __shfl_xor_sync(0xFFFFFFFFu, v, off);
    if (lane == 0) red[tid >> 5] = v;
    __syncthreads();
    if (tid < 32) {
        float s = red[tid];
        #pragma unroll
        for (int off = 16; off > 0; off >>= 1)
            s += __shfl_xor_sync(0xFFFFFFFFu, s, off);
        if (tid == 0) out[0] = 1.f / (1.f + expf(-(s + d2b[0])));
    }
}

// ---------------- launch ----------------
extern "C" void kernel_launch(void* const* d_in, const int* in_sizes, int n_in,
                              void* d_out, int out_size) {
    const void*  sent = d_in[0];
    const float* emb  = (const float*)d_in[1];

    GemmArgs ga; ScanArgs sa;
    for (int d = 0; d < 4; d++) {
        ga.Wih[d] = (const float*)d_in[2 + 4 * d + 0];
        sa.Whh[d] = (const float*)d_in[2 + 4 * d + 1];
        ga.bih[d] = (const float*)d_in[2 + 4 * d + 2];
        sa.bhh[d] = (const float*)d_in[2 + 4 * d + 3];
    }
    const float* d1w = (const float*)d_in[18];
    const float* d1b = (const float*)d_in[19];
    const float* d2w = (const float*)d_in[20];
    const float* d2b = (const float*)d_in[21];
    float* out = (float*)d_out;

    static const size_t scan_smem = (size_t)(RPB * 3 * H + 2 * H) * sizeof(float);
    cudaFuncSetAttribute(k_scan, cudaFuncAttributeMaxDynamicSharedMemorySize,
                         (int)scan_smem);

    k_reset<<<(NDIR * 2 * H + 255) / 256, 256>>>();
    k_gather<<<S, 128>>>(sent, emb);
    k_gemm_gi<<<dim3(S / BM, G3 / BN, NDIR), 256>>>(ga);
    k_scan<<<NDIR * BPD, NTH, scan_smem>>>(sa);
    k_dense1<<<D1 / 8, 256>>>(d1w, d1b);
    k_dense2<<<1, 1024>>>(d2w, d2b, out);
}

// round 9
// speedup vs baseline: 1.6439x; 1.3245x over previous
#include <cuda_runtime.h>
#include <cuda_bf16.h>
#include <math.h>

// Problem constants
#define S   1024
#define E   512
#define H   512
#define G3  1536      // 3*H
#define D1  1024
#define R4  2048      // 4*H
#define VOC 50257

#define NDIR 4
#define BPD  32       // blocks per direction (4*32 = 128 blocks, 1 per SM)
#define RPB  16       // h-rows per block (32*16 = 512)
#define NTH  256      // 8 warps; warp w owns rows {w, w+8}; lane l owns k-chunk [16l,16l+16)
#define ARRIVALS 256  // 8 warps * 32 blocks, one arrival per warp per step

// ---------------- device scratch (no allocations allowed) ----------------
__device__ float g_x[S * E];                 // embedded sequence [S][E]
__device__ float g_gi[NDIR * S * G3];        // input-side gates
__device__ float g_h[NDIR * 2 * H];          // double-buffered hidden state
__device__ float g_hfinal[NDIR * H];         // rep = [ctx_f, ctx_b, qry_f, qry_b]
__device__ float g_h1[D1];                   // dense1 output
__device__ int   g_ctr[NDIR * S];            // per-step arrival counters

// ---------------- sync primitives ----------------
__device__ __forceinline__ int ld_acquire(const int* p) {
    int v;
    asm volatile("ld.acquire.gpu.global.b32 %0, [%1];" : "=r"(v) : "l"(p) : "memory");
    return v;
}
__device__ __forceinline__ void red_release_add1(int* p) {
    asm volatile("red.release.gpu.global.add.s32 [%0], 1;" :: "l"(p) : "memory");
}

// ---------------- fast activations ----------------
__device__ __forceinline__ float fsigmoid(float x) {
    return 1.f / (1.f + __expf(-x));
}
__device__ __forceinline__ float ftanh(float x) {
    return 2.f / (1.f + __expf(-2.f * x)) - 1.f;
}

// ---------------- reset counters ----------------
__global__ void k_reset() {
    int i = blockIdx.x * blockDim.x + threadIdx.x;
    if (i < NDIR * S) g_ctr[i] = 0;
}

// ---------------- embedding gather (with int32/int64 sniffing) ----------------
__global__ void k_gather(const void* __restrict__ sent, const float* __restrict__ emb) {
    __shared__ int is64;
    if (threadIdx.x == 0) {
        const long long* p = (const long long*)sent;
        bool ok = true;
        #pragma unroll
        for (int i = 0; i < 4; i++) {
            long long v = p[i];
            if (v < 0 || v >= VOC) ok = false;
        }
        is64 = ok ? 1 : 0;
    }
    __syncthreads();
    int t = blockIdx.x;
    long long idx = is64 ? ((const long long*)sent)[t]
                         : (long long)((const int*)sent)[t];
    const float4* src = (const float4*)(emb + (size_t)idx * E);
    float4* dst = (float4*)(g_x + (size_t)t * E);
    for (int k = threadIdx.x; k < E / 4; k += blockDim.x) dst[k] = src[k];
}

// ---------------- gi GEMM: gi[d][t][r] = sum_k x[t][k]*Wih[d][r][k] + bih[d][r] ----
struct GemmArgs { const float* Wih[4]; const float* bih[4]; };

#define BM 128
#define BN 128
#define BK 16
__global__ void __launch_bounds__(256) k_gemm_gi(GemmArgs a) {
    int d = blockIdx.z;
    const float* __restrict__ Wih = a.Wih[d];
    const float* __restrict__ bih = a.bih[d];
    float* out = g_gi + (size_t)d * S * G3;

    __shared__ float sA[BK][BM + 4];   // x:   [k][t]
    __shared__ float sB[BK][BN + 4];   // Wih: [k][r]

    int t0 = blockIdx.x * BM;
    int r0 = blockIdx.y * BN;
    int tx = threadIdx.x & 15;         // t-direction (8 rows each)
    int ty = threadIdx.x >> 4;         // r-direction (8 cols each)

    float acc[8][8];
    #pragma unroll
    for (int i = 0; i < 8; i++)
        #pragma unroll
        for (int j = 0; j < 8; j++) acc[i][j] = 0.f;

    int lrow = threadIdx.x >> 2;        // 0..63
    int lk   = (threadIdx.x & 3) * 4;   // 0,4,8,12

    for (int k0 = 0; k0 < E; k0 += BK) {
        #pragma unroll
        for (int i = 0; i < 2; i++) {
            int row = lrow + i * 64;
            float4 va = *(const float4*)(g_x + (size_t)(t0 + row) * E + k0 + lk);
            float4 vb = *(const float4*)(Wih + (size_t)(r0 + row) * E + k0 + lk);
            sA[lk + 0][row] = va.x; sA[lk + 1][row] = va.y;
            sA[lk + 2][row] = va.z; sA[lk + 3][row] = va.w;
            sB[lk + 0][row] = vb.x; sB[lk + 1][row] = vb.y;
            sB[lk + 2][row] = vb.z; sB[lk + 3][row] = vb.w;
        }
        __syncthreads();
        #pragma unroll
        for (int kk = 0; kk < BK; kk++) {
            float ar[8], br[8];
            *(float4*)(ar + 0) = *(const float4*)&sA[kk][tx * 8 + 0];
            *(float4*)(ar + 4) = *(const float4*)&sA[kk][tx * 8 + 4];
            *(float4*)(br + 0) = *(const float4*)&sB[kk][ty * 8 + 0];
            *(float4*)(br + 4) = *(const float4*)&sB[kk][ty * 8 + 4];
            #pragma unroll
            for (int i = 0; i < 8; i++)
                #pragma unroll
                for (int j = 0; j < 8; j++) acc[i][j] = fmaf(ar[i], br[j], acc[i][j]);
        }
        __syncthreads();
    }
    #pragma unroll
    for (int i = 0; i < 8; i++) {
        int t = t0 + tx * 8 + i;
        int r = r0 + ty * 8;
        #pragma unroll
        for (int j4 = 0; j4 < 2; j4++) {
            float4 v;
            v.x = acc[i][j4 * 4 + 0] + __ldg(bih + r + j4 * 4 + 0);
            v.y = acc[i][j4 * 4 + 1] + __ldg(bih + r + j4 * 4 + 1);
            v.z = acc[i][j4 * 4 + 2] + __ldg(bih + r + j4 * 4 + 2);
            v.w = acc[i][j4 * 4 + 3] + __ldg(bih + r + j4 * 4 + 3);
            *(float4*)(out + (size_t)t * G3 + r + j4 * 4) = v;
        }
    }
}

// ---------------- recurrent scan kernel ----------------
// Warp-autonomous: no __syncthreads in the step loop. Warp w owns h-rows
// {hbase+w, hbase+w+8}; lane l owns k-chunk [16l, 16l+16). Weights live in
// registers (96 floats/thread). Sync: per-direction arrival counter in L2.
struct ScanArgs { const float* Whh[4]; const float* bhh[4]; };

__global__ void __launch_bounds__(NTH, 1) k_scan(ScanArgs a) {
    const int blk   = blockIdx.x;
    const int d     = blk / BPD;
    const int b     = blk % BPD;
    const int hbase = b * RPB;

    const float* __restrict__ Whh = a.Whh[d];
    const float* __restrict__ bhh = a.bhh[d];
    const float* __restrict__ gi  = g_gi + (size_t)d * S * G3;
    int* ctr = g_ctr + d * S;
    float* hbank = g_h + (size_t)d * 2 * H;

    const int tid  = threadIdx.x;
    const int lane = tid & 31;
    const int w    = tid >> 5;
    const bool back = (d & 1);

    const int row0 = hbase + w;
    const int row1 = hbase + w + 8;

    // ---- load weights into registers: wreg[jj][g][i] for k = lane*16 + i ----
    float wreg[2][3][16];
    #pragma unroll
    for (int jj = 0; jj < 2; jj++) {
        int row = (jj == 0) ? row0 : row1;
        #pragma unroll
        for (int g = 0; g < 3; g++) {
            const float4* p = (const float4*)(Whh + ((size_t)g * H + row) * H + lane * 16);
            #pragma unroll
            for (int c = 0; c < 4; c++) {
                float4 v = __ldg(p + c);
                wreg[jj][g][c * 4 + 0] = v.x;
                wreg[jj][g][c * 4 + 1] = v.y;
                wreg[jj][g][c * 4 + 2] = v.z;
                wreg[jj][g][c * 4 + 3] = v.w;
            }
        }
    }
    // lane 0 keeps biases + running h for both rows
    float br0 = 0.f, bz0 = 0.f, bn0 = 0.f, hr0 = 0.f;
    float br1 = 0.f, bz1 = 0.f, bn1 = 0.f, hr1 = 0.f;
    if (lane == 0) {
        br0 = bhh[row0]; bz0 = bhh[H + row0]; bn0 = bhh[2 * H + row0];
        br1 = bhh[row1]; bz1 = bhh[H + row1]; bn1 = bhh[2 * H + row1];
    }

    for (int t = 0; t < S; ++t) {
        const int te = back ? (S - 1 - t) : t;

        // lane0: prefetch input-side gates (independent of h)
        float g6[6];
        if (lane == 0) {
            const float* grow = gi + (size_t)te * G3;
            g6[0] = __ldg(grow + row0);
            g6[1] = __ldg(grow + H + row0);
            g6[2] = __ldg(grow + 2 * H + row0);
            g6[3] = __ldg(grow + row1);
            g6[4] = __ldg(grow + H + row1);
            g6[5] = __ldg(grow + 2 * H + row1);
        }

        // wait for previous step, then load h chunk (L1 bypass)
        float hk[16];
        if (t == 0) {
            #pragma unroll
            for (int i = 0; i < 16; i++) hk[i] = 0.f;
        } else {
            const int* c = &ctr[t - 1];
            while (ld_acquire(c) < ARRIVALS) { }
            const float4* hp = (const float4*)(hbank + (size_t)((t - 1) & 1) * H + lane * 16);
            #pragma unroll
            for (int c4 = 0; c4 < 4; c4++) {
                float4 v = __ldcg(hp + c4);
                hk[c4 * 4 + 0] = v.x; hk[c4 * 4 + 1] = v.y;
                hk[c4 * 4 + 2] = v.z; hk[c4 * 4 + 3] = v.w;
            }
        }

        // 6 dot products from register weights
        float dots[6];
        #pragma unroll
        for (int jj = 0; jj < 2; jj++)
            #pragma unroll
            for (int g = 0; g < 3; g++) {
                float acc = 0.f;
                #pragma unroll
                for (int i = 0; i < 16; i++)
                    acc = fmaf(wreg[jj][g][i], hk[i], acc);
                dots[jj * 3 + g] = acc;
            }
        // butterfly reduce all 6 across 32 lanes
        #pragma unroll
        for (int off = 16; off > 0; off >>= 1) {
            #pragma unroll
            for (int i = 0; i < 6; i++)
                dots[i] += __shfl_xor_sync(0xFFFFFFFFu, dots[i], off);
        }

        // lane0: gate math for both rows, publish h, single release arrival
        if (lane == 0) {
            float r0g = fsigmoid(g6[0] + dots[0] + br0);
            float z0g = fsigmoid(g6[1] + dots[1] + bz0);
            float n0g = ftanh(g6[2] + r0g * (dots[2] + bn0));
            float h0n = (1.f - z0g) * n0g + z0g * hr0;
            hr0 = h0n;

            float r1g = fsigmoid(g6[3] + dots[3] + br1);
            float z1g = fsigmoid(g6[4] + dots[4] + bz1);
            float n1g = ftanh(g6[5] + r1g * (dots[5] + bn1));
            float h1n = (1.f - z1g) * n1g + z1g * hr1;
            hr1 = h1n;

            float* hout = hbank + (size_t)(t & 1) * H;
            hout[row0] = h0n;
            hout[row1] = h1n;
            if (t == S - 1) {
                g_hfinal[d * H + row0] = h0n;
                g_hfinal[d * H + row1] = h1n;
            }
            red_release_add1(&ctr[t]);   // release orders the h stores above
        }
    }
}

// ---------------- dense1: h1 = relu(d1_w @ rep + d1_b) ----------------
__global__ void __launch_bounds__(256) k_dense1(const float* __restrict__ d1w,
                                                const float* __restrict__ d1b) {
    int warp = threadIdx.x >> 5, lane = threadIdx.x & 31;
    int row = blockIdx.x * 8 + warp;          // grid 128 -> 1024 rows
    const float* wr = d1w + (size_t)row * R4;
    float acc = 0.f;
    #pragma unroll 8
    for (int k = lane; k < R4; k += 32)
        acc = fmaf(wr[k], g_hfinal[k], acc);
    #pragma unroll
    for (int off = 16; off > 0; off >>= 1)
        acc += __shfl_xor_sync(0xFFFFFFFFu, acc, off);
    if (lane == 0) g_h1[row] = fmaxf(acc + d1b[row], 0.f);
}

// ---------------- dense2: out = sigmoid(d2_w . h1 + d2_b) ----------------
__global__ void __launch_bounds__(1024) k_dense2(const float* __restrict__ d2w,
                                                 const float* __restrict__ d2b,
                                                 float* __restrict__ out) {
    __shared__ float red[32];
    int tid = threadIdx.x, lane = tid & 31;
    float v = g_h1[tid] * d2w[tid];
    #pragma unroll
    for (int off = 16; off > 0; off >>= 1)
        v += __shfl_xor_sync(0xFFFFFFFFu, v, off);
    if (lane == 0) red[tid >> 5] = v;
    __syncthreads();
    if (tid < 32) {
        float s = red[tid];
        #pragma unroll
        for (int off = 16; off > 0; off >>= 1)
            s += __shfl_xor_sync(0xFFFFFFFFu, s, off);
        if (tid == 0) out[0] = 1.f / (1.f + expf(-(s + d2b[0])));
    }
}

// ---------------- launch ----------------
extern "C" void kernel_launch(void* const* d_in, const int* in_sizes, int n_in,
                              void* d_out, int out_size) {
    const void*  sent = d_in[0];
    const float* emb  = (const float*)d_in[1];

    GemmArgs ga; ScanArgs sa;
    for (int d = 0; d < 4; d++) {
        ga.Wih[d] = (const float*)d_in[2 + 4 * d + 0];
        sa.Whh[d] = (const float*)d_in[2 + 4 * d + 1];
        ga.bih[d] = (const float*)d_in[2 + 4 * d + 2];
        sa.bhh[d] = (const float*)d_in[2 + 4 * d + 3];
    }
    const float* d1w = (const float*)d_in[18];
    const float* d1b = (const float*)d_in[19];
    const float* d2w = (const float*)d_in[20];
    const float* d2b = (const float*)d_in[21];
    float* out = (float*)d_out;

    k_reset<<<(NDIR * S + 255) / 256, 256>>>();
    k_gather<<<S, 128>>>(sent, emb);
    k_gemm_gi<<<dim3(S / BM, G3 / BN, NDIR), 256>>>(ga);
    k_scan<<<NDIR * BPD, NTH>>>(sa);
    k_dense1<<<D1 / 8, 256>>>(d1w, d1b);
    k_dense2<<<1, 1024>>>(d2w, d2b, out);
}

// round 10
// speedup vs baseline: 1.8069x; 1.0991x over previous
#include <cuda_runtime.h>
#include <cuda_bf16.h>
#include <math.h>

// Problem constants
#define S   1024
#define E   512
#define H   512
#define G3  1536      // 3*H
#define D1  1024
#define R4  2048      // 4*H
#define VOC 50257

#define NDIR 4
#define BPD  32       // blocks per direction (4*32 = 128 blocks)
#define RPB  16       // h-rows per block (32*16 = 512)
#define NTH  256      // 8 warps; warp w owns rows {w, w+8}; lane l owns k-chunk [16l,16l+16)
#define ARRIVALS 256  // 8 warps * 32 blocks, one arrival per warp per step

// ---------------- device scratch (no allocations allowed) ----------------
__device__ float g_x[S * E];                 // embedded sequence [S][E]
__device__ float g_gi[NDIR * S * G3];        // input-side gates
__device__ float g_h[NDIR * 2 * H];          // double-buffered hidden state
__device__ float g_hfinal[NDIR * H];         // rep = [ctx_f, ctx_b, qry_f, qry_b]
__device__ float g_h1[D1];                   // dense1 output
__device__ int   g_ctr[NDIR * S];            // per-step arrival counters

// ---------------- sync primitives ----------------
__device__ __forceinline__ int ld_acquire(const int* p) {
    int v;
    asm volatile("ld.acquire.gpu.global.b32 %0, [%1];" : "=r"(v) : "l"(p) : "memory");
    return v;
}
__device__ __forceinline__ void red_release_add1(int* p) {
    asm volatile("red.release.gpu.global.add.s32 [%0], 1;" :: "l"(p) : "memory");
}

// ---------------- fast activations ----------------
__device__ __forceinline__ float fsigmoid(float x) {
    return 1.f / (1.f + __expf(-x));
}
__device__ __forceinline__ float ftanh(float x) {
    return 2.f / (1.f + __expf(-2.f * x)) - 1.f;
}

// ---------------- reset counters ----------------
__global__ void k_reset() {
    int i = blockIdx.x * blockDim.x + threadIdx.x;
    if (i < NDIR * S) g_ctr[i] = 0;
}

// ---------------- embedding gather (with int32/int64 sniffing) ----------------
__global__ void k_gather(const void* __restrict__ sent, const float* __restrict__ emb) {
    __shared__ int is64;
    if (threadIdx.x == 0) {
        const long long* p = (const long long*)sent;
        bool ok = true;
        #pragma unroll
        for (int i = 0; i < 4; i++) {
            long long v = p[i];
            if (v < 0 || v >= VOC) ok = false;
        }
        is64 = ok ? 1 : 0;
    }
    __syncthreads();
    int t = blockIdx.x;
    long long idx = is64 ? ((const long long*)sent)[t]
                         : (long long)((const int*)sent)[t];
    const float4* src = (const float4*)(emb + (size_t)idx * E);
    float4* dst = (float4*)(g_x + (size_t)t * E);
    for (int k = threadIdx.x; k < E / 4; k += blockDim.x) dst[k] = src[k];
}

// ---------------- gi GEMM: gi[d][t][r] = sum_k x[t][k]*Wih[d][r][k] + bih[d][r] ----
struct GemmArgs { const float* Wih[4]; const float* bih[4]; };

#define BM 128
#define BN 128
#define BK 16
__global__ void __launch_bounds__(256) k_gemm_gi(GemmArgs a) {
    int d = blockIdx.z;
    const float* __restrict__ Wih = a.Wih[d];
    const float* __restrict__ bih = a.bih[d];
    float* out = g_gi + (size_t)d * S * G3;

    __shared__ float sA[BK][BM + 4];   // x:   [k][t]
    __shared__ float sB[BK][BN + 4];   // Wih: [k][r]

    int t0 = blockIdx.x * BM;
    int r0 = blockIdx.y * BN;
    int tx = threadIdx.x & 15;         // t-direction (8 rows each)
    int ty = threadIdx.x >> 4;         // r-direction (8 cols each)

    float acc[8][8];
    #pragma unroll
    for (int i = 0; i < 8; i++)
        #pragma unroll
        for (int j = 0; j < 8; j++) acc[i][j] = 0.f;

    int lrow = threadIdx.x >> 2;        // 0..63
    int lk   = (threadIdx.x & 3) * 4;   // 0,4,8,12

    for (int k0 = 0; k0 < E; k0 += BK) {
        #pragma unroll
        for (int i = 0; i < 2; i++) {
            int row = lrow + i * 64;
            float4 va = *(const float4*)(g_x + (size_t)(t0 + row) * E + k0 + lk);
            float4 vb = *(const float4*)(Wih + (size_t)(r0 + row) * E + k0 + lk);
            sA[lk + 0][row] = va.x; sA[lk + 1][row] = va.y;
            sA[lk + 2][row] = va.z; sA[lk + 3][row] = va.w;
            sB[lk + 0][row] = vb.x; sB[lk + 1][row] = vb.y;
            sB[lk + 2][row] = vb.z; sB[lk + 3][row] = vb.w;
        }
        __syncthreads();
        #pragma unroll
        for (int kk = 0; kk < BK; kk++) {
            float ar[8], br[8];
            *(float4*)(ar + 0) = *(const float4*)&sA[kk][tx * 8 + 0];
            *(float4*)(ar + 4) = *(const float4*)&sA[kk][tx * 8 + 4];
            *(float4*)(br + 0) = *(const float4*)&sB[kk][ty * 8 + 0];
            *(float4*)(br + 4) = *(const float4*)&sB[kk][ty * 8 + 4];
            #pragma unroll
            for (int i = 0; i < 8; i++)
                #pragma unroll
                for (int j = 0; j < 8; j++) acc[i][j] = fmaf(ar[i], br[j], acc[i][j]);
        }
        __syncthreads();
    }
    #pragma unroll
    for (int i = 0; i < 8; i++) {
        int t = t0 + tx * 8 + i;
        int r = r0 + ty * 8;
        #pragma unroll
        for (int j4 = 0; j4 < 2; j4++) {
            float4 v;
            v.x = acc[i][j4 * 4 + 0] + __ldg(bih + r + j4 * 4 + 0);
            v.y = acc[i][j4 * 4 + 1] + __ldg(bih + r + j4 * 4 + 1);
            v.z = acc[i][j4 * 4 + 2] + __ldg(bih + r + j4 * 4 + 2);
            v.w = acc[i][j4 * 4 + 3] + __ldg(bih + r + j4 * 4 + 3);
            *(float4*)(out + (size_t)t * G3 + r + j4 * 4) = v;
        }
    }
}

// ---------------- recurrent scan kernel ----------------
// Warp w owns h-rows {hbase+w, hbase+w+8}; lane l owns k-chunk [16l, 16l+16).
// Whh lives in registers (96 floats/thread). Sync per step:
//   consumer: ONLY tid0 polls the arrival counter (32 pollers/direction,
//             coalesced) then __syncthreads broadcasts;
//   producer: lane0 st.cg h (2 rows) then red.release arrival (orders stores).
struct ScanArgs { const float* Whh[4]; const float* bhh[4]; };

__global__ void __launch_bounds__(NTH, 1) k_scan(ScanArgs a) {
    const int blk   = blockIdx.x;
    const int d     = blk / BPD;
    const int b     = blk % BPD;
    const int hbase = b * RPB;

    const float* __restrict__ Whh = a.Whh[d];
    const float* __restrict__ bhh = a.bhh[d];
    const float* __restrict__ gi  = g_gi + (size_t)d * S * G3;
    int* ctr = g_ctr + d * S;
    float* hbank = g_h + (size_t)d * 2 * H;

    const int tid  = threadIdx.x;
    const int lane = tid & 31;
    const int w    = tid >> 5;
    const bool back = (d & 1);

    const int row0 = hbase + w;
    const int row1 = hbase + w + 8;

    // ---- load weights into registers: wreg[jj][g][i] for k = lane*16 + i ----
    float wreg[2][3][16];
    #pragma unroll
    for (int jj = 0; jj < 2; jj++) {
        int row = (jj == 0) ? row0 : row1;
        #pragma unroll
        for (int g = 0; g < 3; g++) {
            const float4* p = (const float4*)(Whh + ((size_t)g * H + row) * H + lane * 16);
            #pragma unroll
            for (int c = 0; c < 4; c++) {
                float4 v = __ldg(p + c);
                wreg[jj][g][c * 4 + 0] = v.x;
                wreg[jj][g][c * 4 + 1] = v.y;
                wreg[jj][g][c * 4 + 2] = v.z;
                wreg[jj][g][c * 4 + 3] = v.w;
            }
        }
    }
    // lane 0 keeps biases + running h for both rows
    float br0 = 0.f, bz0 = 0.f, bn0 = 0.f, hr0 = 0.f;
    float br1 = 0.f, bz1 = 0.f, bn1 = 0.f, hr1 = 0.f;
    if (lane == 0) {
        br0 = bhh[row0]; bz0 = bhh[H + row0]; bn0 = bhh[2 * H + row0];
        br1 = bhh[row1]; bz1 = bhh[H + row1]; bn1 = bhh[2 * H + row1];
    }

    for (int t = 0; t < S; ++t) {
        const int te = back ? (S - 1 - t) : t;

        // lane0: prefetch input-side gates (independent of h, before the wait)
        float g6[6];
        if (lane == 0) {
            const float* grow = gi + (size_t)te * G3;
            g6[0] = __ldg(grow + row0);
            g6[1] = __ldg(grow + H + row0);
            g6[2] = __ldg(grow + 2 * H + row0);
            g6[3] = __ldg(grow + row1);
            g6[4] = __ldg(grow + H + row1);
            g6[5] = __ldg(grow + 2 * H + row1);
        }

        // single-poller wait + block broadcast
        if (t > 0) {
            if (tid == 0) {
                const int* c = &ctr[t - 1];
                while (ld_acquire(c) < ARRIVALS) { }
            }
            __syncthreads();   // the only barrier per step
        }

        // load h chunk (L1 bypass; other SMs wrote it)
        float hk[16];
        if (t == 0) {
            #pragma unroll
            for (int i = 0; i < 16; i++) hk[i] = 0.f;
        } else {
            const float4* hp = (const float4*)(hbank + (size_t)((t - 1) & 1) * H + lane * 16);
            #pragma unroll
            for (int c4 = 0; c4 < 4; c4++) {
                float4 v = __ldcg(hp + c4);
                hk[c4 * 4 + 0] = v.x; hk[c4 * 4 + 1] = v.y;
                hk[c4 * 4 + 2] = v.z; hk[c4 * 4 + 3] = v.w;
            }
        }

        // 6 dot products from register weights
        float dots[6];
        #pragma unroll
        for (int jj = 0; jj < 2; jj++)
            #pragma unroll
            for (int g = 0; g < 3; g++) {
                float acc = 0.f;
                #pragma unroll
                for (int i = 0; i < 16; i++)
                    acc = fmaf(wreg[jj][g][i], hk[i], acc);
                dots[jj * 3 + g] = acc;
            }
        // butterfly reduce all 6 across 32 lanes
        #pragma unroll
        for (int off = 16; off > 0; off >>= 1) {
            #pragma unroll
            for (int i = 0; i < 6; i++)
                dots[i] += __shfl_xor_sync(0xFFFFFFFFu, dots[i], off);
        }

        // lane0: gate math for both rows, publish h, single release arrival
        if (lane == 0) {
            float r0g = fsigmoid(g6[0] + dots[0] + br0);
            float z0g = fsigmoid(g6[1] + dots[1] + bz0);
            float n0g = ftanh(g6[2] + r0g * (dots[2] + bn0));
            float h0n = (1.f - z0g) * n0g + z0g * hr0;
            hr0 = h0n;

            float r1g = fsigmoid(g6[3] + dots[3] + br1);
            float z1g = fsigmoid(g6[4] + dots[4] + bz1);
            float n1g = ftanh(g6[5] + r1g * (dots[5] + bn1));
            float h1n = (1.f - z1g) * n1g + z1g * hr1;
            hr1 = h1n;

            float* hout = hbank + (size_t)(t & 1) * H;
            __stcg(hout + row0, h0n);
            __stcg(hout + row1, h1n);
            if (t == S - 1) {
                g_hfinal[d * H + row0] = h0n;
                g_hfinal[d * H + row1] = h1n;
            }
            red_release_add1(&ctr[t]);   // release orders the h stores above
        }
    }
}

// ---------------- dense1: h1 = relu(d1_w @ rep + d1_b) ----------------
__global__ void __launch_bounds__(256) k_dense1(const float* __restrict__ d1w,
                                                const float* __restrict__ d1b) {
    int warp = threadIdx.x >> 5, lane = threadIdx.x & 31;
    int row = blockIdx.x * 8 + warp;          // grid 128 -> 1024 rows
    const float* wr = d1w + (size_t)row * R4;
    float acc = 0.f;
    #pragma unroll 8
    for (int k = lane; k < R4; k += 32)
        acc = fmaf(wr[k], g_hfinal[k], acc);
    #pragma unroll
    for (int off = 16; off > 0; off >>= 1)
        acc += __shfl_xor_sync(0xFFFFFFFFu, acc, off);
    if (lane == 0) g_h1[row] = fmaxf(acc + d1b[row], 0.f);
}

// ---------------- dense2: out = sigmoid(d2_w . h1 + d2_b) ----------------
__global__ void __launch_bounds__(1024) k_dense2(const float* __restrict__ d2w,
                                                 const float* __restrict__ d2b,
                                                 float* __restrict__ out) {
    __shared__ float red[32];
    int tid = threadIdx.x, lane = tid & 31;
    float v = g_h1[tid] * d2w[tid];
    #pragma unroll
    for (int off = 16; off > 0; off >>= 1)
        v += __shfl_xor_sync(0xFFFFFFFFu, v, off);
    if (lane == 0) red[tid >> 5] = v;
    __syncthreads();
    if (tid < 32) {
        float s = red[tid];
        #pragma unroll
        for (int off = 16; off > 0; off >>= 1)
            s += __shfl_xor_sync(0xFFFFFFFFu, s, off);
        if (tid == 0) out[0] = 1.f / (1.f + expf(-(s + d2b[0])));
    }
}

// ---------------- launch ----------------
extern "C" void kernel_launch(void* const* d_in, const int* in_sizes, int n_in,
                              void* d_out, int out_size) {
    const void*  sent = d_in[0];
    const float* emb  = (const float*)d_in[1];

    GemmArgs ga; ScanArgs sa;
    for (int d = 0; d < 4; d++) {
        ga.Wih[d] = (const float*)d_in[2 + 4 * d + 0];
        sa.Whh[d] = (const float*)d_in[2 + 4 * d + 1];
        ga.bih[d] = (const float*)d_in[2 + 4 * d + 2];
        sa.bhh[d] = (const float*)d_in[2 + 4 * d + 3];
    }
    const float* d1w = (const float*)d_in[18];
    const float* d1b = (const float*)d_in[19];
    const float* d2w = (const float*)d_in[20];
    const float* d2b = (const float*)d_in[21];
    float* out = (float*)d_out;

    k_reset<<<(NDIR * S + 255) / 256, 256>>>();
    k_gather<<<S, 128>>>(sent, emb);
    k_gemm_gi<<<dim3(S / BM, G3 / BN, NDIR), 256>>>(ga);
    k_scan<<<NDIR * BPD, NTH>>>(sa);
    k_dense1<<<D1 / 8, 256>>>(d1w, d1b);
    k_dense2<<<1, 1024>>>(d2w, d2b, out);
}

// round 14
// speedup vs baseline: 1.8654x; 1.0324x over previous
#include <cuda_runtime.h>
#include <cuda_bf16.h>
#include <math.h>

// Problem constants
#define S   1024
#define E   512
#define H   512
#define G3  1536      // 3*H
#define D1  1024
#define R4  2048      // 4*H
#define VOC 50257

#define NDIR 4
#define BPD  32       // blocks per direction (4*32 = 128 blocks)
#define RPB  16       // h-rows per block (32*16 = 512)
#define NTH  256      // 8 warps; warp w owns rows {w, w+8}; lane l owns k-chunk [16l,16l+16)

// ---------------- device scratch (no allocations allowed) ----------------
__device__ float g_x[S * E];                 // embedded sequence [S][E]
__device__ float g_gi[NDIR * S * G3];        // input-side gates
__device__ float g_h[NDIR * 2 * H];          // double-buffered hidden state
__device__ float g_hfinal[NDIR * H];         // rep = [ctx_f, ctx_b, qry_f, qry_b]
__device__ float g_h1[D1];                   // dense1 output
__device__ __align__(128) int g_tag[NDIR * BPD];  // per-block monotonic step tags
                                                  // (one 128B line per direction)

// ---------------- sync primitives (NO atomics) ----------------
__device__ __forceinline__ int ld_acquire(const int* p) {
    int v;
    asm volatile("ld.acquire.gpu.global.b32 %0, [%1];" : "=r"(v) : "l"(p) : "memory");
    return v;
}
__device__ __forceinline__ void st_release(int* p, int v) {
    asm volatile("st.release.gpu.global.b32 [%0], %1;" :: "l"(p), "r"(v) : "memory");
}

// ---------------- fast activations ----------------
__device__ __forceinline__ float fsigmoid(float x) {
    return 1.f / (1.f + __expf(-x));
}
__device__ __forceinline__ float ftanh(float x) {
    return 2.f / (1.f + __expf(-2.f * x)) - 1.f;
}

// ---------------- reset tags (every graph replay) ----------------
__global__ void k_reset() {
    int i = blockIdx.x * blockDim.x + threadIdx.x;
    if (i < NDIR * BPD) g_tag[i] = 0;
}

// ---------------- embedding gather (with int32/int64 sniffing) ----------------
__global__ void k_gather(const void* __restrict__ sent, const float* __restrict__ emb) {
    __shared__ int is64;
    if (threadIdx.x == 0) {
        const long long* p = (const long long*)sent;
        bool ok = true;
        #pragma unroll
        for (int i = 0; i < 4; i++) {
            long long v = p[i];
            if (v < 0 || v >= VOC) ok = false;
        }
        is64 = ok ? 1 : 0;
    }
    __syncthreads();
    int t = blockIdx.x;
    long long idx = is64 ? ((const long long*)sent)[t]
                         : (long long)((const int*)sent)[t];
    const float4* src = (const float4*)(emb + (size_t)idx * E);
    float4* dst = (float4*)(g_x + (size_t)t * E);
    for (int k = threadIdx.x; k < E / 4; k += blockDim.x) dst[k] = src[k];
}

// ---------------- gi GEMM: gi[d][t][r] = sum_k x[t][k]*Wih[d][r][k] + bih[d][r] ----
struct GemmArgs { const float* Wih[4]; const float* bih[4]; };

#define BM 128
#define BN 128
#define BK 16
__global__ void __launch_bounds__(256) k_gemm_gi(GemmArgs a) {
    int d = blockIdx.z;
    const float* __restrict__ Wih = a.Wih[d];
    const float* __restrict__ bih = a.bih[d];
    float* out = g_gi + (size_t)d * S * G3;

    __shared__ float sA[BK][BM + 4];   // x:   [k][t]
    __shared__ float sB[BK][BN + 4];   // Wih: [k][r]

    int t0 = blockIdx.x * BM;
    int r0 = blockIdx.y * BN;
    int tx = threadIdx.x & 15;         // t-direction (8 rows each)
    int ty = threadIdx.x >> 4;         // r-direction (8 cols each)

    float acc[8][8];
    #pragma unroll
    for (int i = 0; i < 8; i++)
        #pragma unroll
        for (int j = 0; j < 8; j++) acc[i][j] = 0.f;

    int lrow = threadIdx.x >> 2;        // 0..63
    int lk   = (threadIdx.x & 3) * 4;   // 0,4,8,12

    for (int k0 = 0; k0 < E; k0 += BK) {
        #pragma unroll
        for (int i = 0; i < 2; i++) {
            int row = lrow + i * 64;
            float4 va = *(const float4*)(g_x + (size_t)(t0 + row) * E + k0 + lk);
            float4 vb = *(const float4*)(Wih + (size_t)(r0 + row) * E + k0 + lk);
            sA[lk + 0][row] = va.x; sA[lk + 1][row] = va.y;
            sA[lk + 2][row] = va.z; sA[lk + 3][row] = va.w;
            sB[lk + 0][row] = vb.x; sB[lk + 1][row] = vb.y;
            sB[lk + 2][row] = vb.z; sB[lk + 3][row] = vb.w;
        }
        __syncthreads();
        #pragma unroll
        for (int kk = 0; kk < BK; kk++) {
            float ar[8], br[8];
            *(float4*)(ar + 0) = *(const float4*)&sA[kk][tx * 8 + 0];
            *(float4*)(ar + 4) = *(const float4*)&sA[kk][tx * 8 + 4];
            *(float4*)(br + 0) = *(const float4*)&sB[kk][ty * 8 + 0];
            *(float4*)(br + 4) = *(const float4*)&sB[kk][ty * 8 + 4];
            #pragma unroll
            for (int i = 0; i < 8; i++)
                #pragma unroll
                for (int j = 0; j < 8; j++) acc[i][j] = fmaf(ar[i], br[j], acc[i][j]);
        }
        __syncthreads();
    }
    #pragma unroll
    for (int i = 0; i < 8; i++) {
        int t = t0 + tx * 8 + i;
        int r = r0 + ty * 8;
        #pragma unroll
        for (int j4 = 0; j4 < 2; j4++) {
            float4 v;
            v.x = acc[i][j4 * 4 + 0] + __ldg(bih + r + j4 * 4 + 0);
            v.y = acc[i][j4 * 4 + 1] + __ldg(bih + r + j4 * 4 + 1);
            v.z = acc[i][j4 * 4 + 2] + __ldg(bih + r + j4 * 4 + 2);
            v.w = acc[i][j4 * 4 + 3] + __ldg(bih + r + j4 * 4 + 3);
            *(float4*)(out + (size_t)t * G3 + r + j4 * 4) = v;
        }
    }
}

// ---------------- recurrent scan kernel ----------------
// Sync protocol (no atomics): per direction, 32 tag words in ONE 128B line.
// Block b publishes its 16 h floats (st.cg, 64B) then st.release tag[b]=t+1.
// Consumers: warp0's lane b spins on tag[b] (one coalesced line-load per
// sweep), __syncthreads broadcasts, then all warps __ldcg the h buffer.
// Safety: monotonic tags; tag>=t from block c certifies c finished READING
// buffer parity (t-1)&1, so overwrites at parity (t+1)&1 are race-free.
struct ScanArgs { const float* Whh[4]; const float* bhh[4]; };

__global__ void __launch_bounds__(NTH, 1) k_scan(ScanArgs a) {
    __shared__ float hstage[RPB];   // block's 16 new h values

    const int blk   = blockIdx.x;
    const int d     = blk / BPD;
    const int b     = blk % BPD;
    const int hbase = b * RPB;

    const float* __restrict__ Whh = a.Whh[d];
    const float* __restrict__ bhh = a.bhh[d];
    const float* __restrict__ gi  = g_gi + (size_t)d * S * G3;
    int* tagline = g_tag + d * BPD;
    float* hbank = g_h + (size_t)d * 2 * H;

    const int tid  = threadIdx.x;
    const int lane = tid & 31;
    const int w    = tid >> 5;
    const bool back = (d & 1);

    const int row0 = hbase + w;
    const int row1 = hbase + w + 8;

    // ---- load weights into registers: wreg[jj][g][i] for k = lane*16 + i ----
    float wreg[2][3][16];
    #pragma unroll
    for (int jj = 0; jj < 2; jj++) {
        int row = (jj == 0) ? row0 : row1;
        #pragma unroll
        for (int g = 0; g < 3; g++) {
            const float4* p = (const float4*)(Whh + ((size_t)g * H + row) * H + lane * 16);
            #pragma unroll
            for (int c = 0; c < 4; c++) {
                float4 v = __ldg(p + c);
                wreg[jj][g][c * 4 + 0] = v.x;
                wreg[jj][g][c * 4 + 1] = v.y;
                wreg[jj][g][c * 4 + 2] = v.z;
                wreg[jj][g][c * 4 + 3] = v.w;
            }
        }
    }
    // lane 0 keeps biases + running h for both rows
    float br0 = 0.f, bz0 = 0.f, bn0 = 0.f, hr0 = 0.f;
    float br1 = 0.f, bz1 = 0.f, bn1 = 0.f, hr1 = 0.f;
    if (lane == 0) {
        br0 = bhh[row0]; bz0 = bhh[H + row0]; bn0 = bhh[2 * H + row0];
        br1 = bhh[row1]; bz1 = bhh[H + row1]; bn1 = bhh[2 * H + row1];
    }

    for (int t = 0; t < S; ++t) {
        const int te = back ? (S - 1 - t) : t;

        // lane0: prefetch input-side gates (independent of h, before the wait)
        float g6[6];
        if (lane == 0) {
            const float* grow = gi + (size_t)te * G3;
            g6[0] = __ldg(grow + row0);
            g6[1] = __ldg(grow + H + row0);
            g6[2] = __ldg(grow + 2 * H + row0);
            g6[3] = __ldg(grow + row1);
            g6[4] = __ldg(grow + H + row1);
            g6[5] = __ldg(grow + 2 * H + row1);
        }

        float hk[16];
        if (t == 0) {
            #pragma unroll
            for (int i = 0; i < 16; i++) hk[i] = 0.f;
        } else {
            // warp0: each lane spins on its own tag word (one line, coalesced)
            if (w == 0) {
                const int* tp = tagline + lane;
                while (ld_acquire(tp) < t) { }
            }
            __syncthreads();   // barrier 1: h(t-1) visible to all warps

            const float4* hp = (const float4*)(hbank + (size_t)((t - 1) & 1) * H + lane * 16);
            #pragma unroll
            for (int c4 = 0; c4 < 4; c4++) {
                float4 v = __ldcg(hp + c4);
                hk[c4 * 4 + 0] = v.x; hk[c4 * 4 + 1] = v.y;
                hk[c4 * 4 + 2] = v.z; hk[c4 * 4 + 3] = v.w;
            }
        }

        // 6 dot products from register weights
        float dots[6];
        #pragma unroll
        for (int jj = 0; jj < 2; jj++)
            #pragma unroll
            for (int g = 0; g < 3; g++) {
                float acc = 0.f;
                #pragma unroll
                for (int i = 0; i < 16; i++)
                    acc = fmaf(wreg[jj][g][i], hk[i], acc);
                dots[jj * 3 + g] = acc;
            }
        // butterfly reduce all 6 across 32 lanes
        #pragma unroll
        for (int off = 16; off > 0; off >>= 1) {
            #pragma unroll
            for (int i = 0; i < 6; i++)
                dots[i] += __shfl_xor_sync(0xFFFFFFFFu, dots[i], off);
        }

        // lane0: gate math for both rows -> smem stage
        if (lane == 0) {
            float r0g = fsigmoid(g6[0] + dots[0] + br0);
            float z0g = fsigmoid(g6[1] + dots[1] + bz0);
            float n0g = ftanh(g6[2] + r0g * (dots[2] + bn0));
            float h0n = (1.f - z0g) * n0g + z0g * hr0;
            hr0 = h0n;

            float r1g = fsigmoid(g6[3] + dots[3] + br1);
            float z1g = fsigmoid(g6[4] + dots[4] + bz1);
            float n1g = ftanh(g6[5] + r1g * (dots[5] + bn1));
            float h1n = (1.f - z1g) * n1g + z1g * hr1;
            hr1 = h1n;

            hstage[w]     = h0n;
            hstage[w + 8] = h1n;
            if (t == S - 1) {
                g_hfinal[d * H + row0] = h0n;
                g_hfinal[d * H + row1] = h1n;
            }
        }
        __syncthreads();   // barrier 2: hstage complete

        // tid0: publish 64B of h data + release the tag (plain stores, no RMW)
        if (tid == 0) {
            const float4* hs = (const float4*)hstage;
            float4 v0 = hs[0], v1 = hs[1], v2 = hs[2], v3 = hs[3];
            float4* hout = (float4*)(hbank + (size_t)(t & 1) * H + hbase);
            __stcg(hout + 0, v0);
            __stcg(hout + 1, v1);
            __stcg(hout + 2, v2);
            __stcg(hout + 3, v3);
            st_release(tagline + b, t + 1);   // orders the 4 data stores
        }
    }
}

// ---------------- dense1: h1 = relu(d1_w @ rep + d1_b) ----------------
__global__ void __launch_bounds__(256) k_dense1(const float* __restrict__ d1w,
                                                const float* __restrict__ d1b) {
    int warp = threadIdx.x >> 5, lane = threadIdx.x & 31;
    int row = blockIdx.x * 8 + warp;          // grid 128 -> 1024 rows
    const float* wr = d1w + (size_t)row * R4;
    float acc = 0.f;
    #pragma unroll 8
    for (int k = lane; k < R4; k += 32)
        acc = fmaf(wr[k], g_hfinal[k], acc);
    #pragma unroll
    for (int off = 16; off > 0; off >>= 1)
        acc += __shfl_xor_sync(0xFFFFFFFFu, acc, off);
    if (lane == 0) g_h1[row] = fmaxf(acc + d1b[row], 0.f);
}

// ---------------- dense2: out = sigmoid(d2_w . h1 + d2_b) ----------------
__global__ void __launch_bounds__(1024) k_dense2(const float* __restrict__ d2w,
                                                 const float* __restrict__ d2b,
                                                 float* __restrict__ out) {
    __shared__ float red[32];
    int tid = threadIdx.x, lane = tid & 31;
    float v = g_h1[tid] * d2w[tid];
    #pragma unroll
    for (int off = 16; off > 0; off >>= 1)
        v += __shfl_xor_sync(0xFFFFFFFFu, v, off);
    if (lane == 0) red[tid >> 5] = v;
    __syncthreads();
    if (tid < 32) {
        float s = red[tid];
        #pragma unroll
        for (int off = 16; off > 0; off >>= 1)
            s += __shfl_xor_sync(0xFFFFFFFFu, s, off);
        if (tid == 0) out[0] = 1.f / (1.f + expf(-(s + d2b[0])));
    }
}

// ---------------- launch ----------------
extern "C" void kernel_launch(void* const* d_in, const int* in_sizes, int n_in,
                              void* d_out, int out_size) {
    const void*  sent = d_in[0];
    const float* emb  = (const float*)d_in[1];

    GemmArgs ga; ScanArgs sa;
    for (int d = 0; d < 4; d++) {
        ga.Wih[d] = (const float*)d_in[2 + 4 * d + 0];
        sa.Whh[d] = (const float*)d_in[2 + 4 * d + 1];
        ga.bih[d] = (const float*)d_in[2 + 4 * d + 2];
        sa.bhh[d] = (const float*)d_in[2 + 4 * d + 3];
    }
    const float* d1w = (const float*)d_in[18];
    const float* d1b = (const float*)d_in[19];
    const float* d2w = (const float*)d_in[20];
    const float* d2b = (const float*)d_in[21];
    float* out = (float*)d_out;

    k_reset<<<1, 128>>>();
    k_gather<<<S, 128>>>(sent, emb);
    k_gemm_gi<<<dim3(S / BM, G3 / BN, NDIR), 256>>>(ga);
    k_scan<<<NDIR * BPD, NTH>>>(sa);
    k_dense1<<<D1 / 8, 256>>>(d1w, d1b);
    k_dense2<<<1, 1024>>>(d2w, d2b, out);
}

// round 15
// speedup vs baseline: 1.9944x; 1.0692x over previous
#include <cuda_runtime.h>
#include <cuda_bf16.h>
#include <math.h>

// Problem constants
#define S   1024
#define E   512
#define H   512
#define G3  1536      // 3*H
#define D1  1024
#define R4  2048      // 4*H
#define VOC 50257

#define NDIR 4
#define BPD  32       // blocks per direction (4*32 = 128 blocks)
#define RPB  16       // h-rows per block (32*16 = 512)
#define NTH  256      // 8 warps; warp w owns rows {w, w+8}; lane l owns k-chunk [16l,16l+16)

// ---------------- device scratch (no allocations allowed) ----------------
__device__ float g_x[S * E];                 // embedded sequence [S][E]
__device__ float g_gi[NDIR * S * G3];        // input-side gates
__device__ float g_h[NDIR * 2 * H];          // double-buffered hidden state
__device__ float g_hfinal[NDIR * H];         // rep = [ctx_f, ctx_b, qry_f, qry_b]
__device__ float g_h1[D1];                   // dense1 output
__device__ __align__(128) int g_tag[NDIR * BPD];  // per-block monotonic step tags
                                                  // (one 128B line per direction)

// ---------------- sync primitives (NO atomics) ----------------
__device__ __forceinline__ int ld_acquire(const int* p) {
    int v;
    asm volatile("ld.acquire.gpu.global.b32 %0, [%1];" : "=r"(v) : "l"(p) : "memory");
    return v;
}
__device__ __forceinline__ void st_release(int* p, int v) {
    asm volatile("st.release.gpu.global.b32 [%0], %1;" :: "l"(p), "r"(v) : "memory");
}

// ---------------- fast activations ----------------
__device__ __forceinline__ float fsigmoid(float x) {
    return 1.f / (1.f + __expf(-x));
}
__device__ __forceinline__ float ftanh(float x) {
    return 2.f / (1.f + __expf(-2.f * x)) - 1.f;
}

// ---------------- reset tags (every graph replay) ----------------
__global__ void k_reset() {
    int i = blockIdx.x * blockDim.x + threadIdx.x;
    if (i < NDIR * BPD) g_tag[i] = 0;
}

// ---------------- embedding gather (with int32/int64 sniffing) ----------------
__global__ void k_gather(const void* __restrict__ sent, const float* __restrict__ emb) {
    __shared__ int is64;
    if (threadIdx.x == 0) {
        const long long* p = (const long long*)sent;
        bool ok = true;
        #pragma unroll
        for (int i = 0; i < 4; i++) {
            long long v = p[i];
            if (v < 0 || v >= VOC) ok = false;
        }
        is64 = ok ? 1 : 0;
    }
    __syncthreads();
    int t = blockIdx.x;
    long long idx = is64 ? ((const long long*)sent)[t]
                         : (long long)((const int*)sent)[t];
    const float4* src = (const float4*)(emb + (size_t)idx * E);
    float4* dst = (float4*)(g_x + (size_t)t * E);
    for (int k = threadIdx.x; k < E / 4; k += blockDim.x) dst[k] = src[k];
}

// ---------------- gi GEMM: gi[d][t][r] = sum_k x[t][k]*Wih[d][r][k] + bih[d][r] ----
struct GemmArgs { const float* Wih[4]; const float* bih[4]; };

#define BM 128
#define BN 128
#define BK 16
__global__ void __launch_bounds__(256) k_gemm_gi(GemmArgs a) {
    int d = blockIdx.z;
    const float* __restrict__ Wih = a.Wih[d];
    const float* __restrict__ bih = a.bih[d];
    float* out = g_gi + (size_t)d * S * G3;

    __shared__ float sA[BK][BM + 4];   // x:   [k][t]
    __shared__ float sB[BK][BN + 4];   // Wih: [k][r]

    int t0 = blockIdx.x * BM;
    int r0 = blockIdx.y * BN;
    int tx = threadIdx.x & 15;         // t-direction (8 rows each)
    int ty = threadIdx.x >> 4;         // r-direction (8 cols each)

    float acc[8][8];
    #pragma unroll
    for (int i = 0; i < 8; i++)
        #pragma unroll
        for (int j = 0; j < 8; j++) acc[i][j] = 0.f;

    int lrow = threadIdx.x >> 2;        // 0..63
    int lk   = (threadIdx.x & 3) * 4;   // 0,4,8,12

    for (int k0 = 0; k0 < E; k0 += BK) {
        #pragma unroll
        for (int i = 0; i < 2; i++) {
            int row = lrow + i * 64;
            float4 va = *(const float4*)(g_x + (size_t)(t0 + row) * E + k0 + lk);
            float4 vb = *(const float4*)(Wih + (size_t)(r0 + row) * E + k0 + lk);
            sA[lk + 0][row] = va.x; sA[lk + 1][row] = va.y;
            sA[lk + 2][row] = va.z; sA[lk + 3][row] = va.w;
            sB[lk + 0][row] = vb.x; sB[lk + 1][row] = vb.y;
            sB[lk + 2][row] = vb.z; sB[lk + 3][row] = vb.w;
        }
        __syncthreads();
        #pragma unroll
        for (int kk = 0; kk < BK; kk++) {
            float ar[8], br[8];
            *(float4*)(ar + 0) = *(const float4*)&sA[kk][tx * 8 + 0];
            *(float4*)(ar + 4) = *(const float4*)&sA[kk][tx * 8 + 4];
            *(float4*)(br + 0) = *(const float4*)&sB[kk][ty * 8 + 0];
            *(float4*)(br + 4) = *(const float4*)&sB[kk][ty * 8 + 4];
            #pragma unroll
            for (int i = 0; i < 8; i++)
                #pragma unroll
                for (int j = 0; j < 8; j++) acc[i][j] = fmaf(ar[i], br[j], acc[i][j]);
        }
        __syncthreads();
    }
    #pragma unroll
    for (int i = 0; i < 8; i++) {
        int t = t0 + tx * 8 + i;
        int r = r0 + ty * 8;
        #pragma unroll
        for (int j4 = 0; j4 < 2; j4++) {
            float4 v;
            v.x = acc[i][j4 * 4 + 0] + __ldg(bih + r + j4 * 4 + 0);
            v.y = acc[i][j4 * 4 + 1] + __ldg(bih + r + j4 * 4 + 1);
            v.z = acc[i][j4 * 4 + 2] + __ldg(bih + r + j4 * 4 + 2);
            v.w = acc[i][j4 * 4 + 3] + __ldg(bih + r + j4 * 4 + 3);
            *(float4*)(out + (size_t)t * G3 + r + j4 * 4) = v;
        }
    }
}

// ---------------- recurrent scan kernel ----------------
// Sync: per direction, 32 tag words in ONE 128B line; block b st.release's
// tag[b]=t+1 after 4 st.cg float4 h stores. Consumer: warp0's lane b polls
// tag[b] with nanosleep backoff (low LTS traffic), loads h from L2 ONCE,
// stages to smem; warps 1-7 read h from smem.
struct ScanArgs { const float* Whh[4]; const float* bhh[4]; };

__global__ void __launch_bounds__(NTH, 1) k_scan(ScanArgs a) {
    __shared__ float hsh[H];        // broadcast h(t-1) staged by warp 0
    __shared__ float hstage[RPB];   // block's 16 new h values

    const int blk   = blockIdx.x;
    const int d     = blk / BPD;
    const int b     = blk % BPD;
    const int hbase = b * RPB;

    const float* __restrict__ Whh = a.Whh[d];
    const float* __restrict__ bhh = a.bhh[d];
    const float* __restrict__ gi  = g_gi + (size_t)d * S * G3;
    int* tagline = g_tag + d * BPD;
    float* hbank = g_h + (size_t)d * 2 * H;

    const int tid  = threadIdx.x;
    const int lane = tid & 31;
    const int w    = tid >> 5;
    const bool back = (d & 1);

    const int row0 = hbase + w;
    const int row1 = hbase + w + 8;

    // ---- load weights into registers: wreg[jj][g][i] for k = lane*16 + i ----
    float wreg[2][3][16];
    #pragma unroll
    for (int jj = 0; jj < 2; jj++) {
        int row = (jj == 0) ? row0 : row1;
        #pragma unroll
        for (int g = 0; g < 3; g++) {
            const float4* p = (const float4*)(Whh + ((size_t)g * H + row) * H + lane * 16);
            #pragma unroll
            for (int c = 0; c < 4; c++) {
                float4 v = __ldg(p + c);
                wreg[jj][g][c * 4 + 0] = v.x;
                wreg[jj][g][c * 4 + 1] = v.y;
                wreg[jj][g][c * 4 + 2] = v.z;
                wreg[jj][g][c * 4 + 3] = v.w;
            }
        }
    }
    // lane 0 keeps biases + running h for both rows
    float br0 = 0.f, bz0 = 0.f, bn0 = 0.f, hr0 = 0.f;
    float br1 = 0.f, bz1 = 0.f, bn1 = 0.f, hr1 = 0.f;
    if (lane == 0) {
        br0 = bhh[row0]; bz0 = bhh[H + row0]; bn0 = bhh[2 * H + row0];
        br1 = bhh[row1]; bz1 = bhh[H + row1]; bn1 = bhh[2 * H + row1];
    }

    for (int t = 0; t < S; ++t) {
        const int te = back ? (S - 1 - t) : t;

        // lane0: prefetch input-side gates (independent of h, before the wait)
        float g6[6];
        if (lane == 0) {
            const float* grow = gi + (size_t)te * G3;
            g6[0] = __ldg(grow + row0);
            g6[1] = __ldg(grow + H + row0);
            g6[2] = __ldg(grow + 2 * H + row0);
            g6[3] = __ldg(grow + row1);
            g6[4] = __ldg(grow + H + row1);
            g6[5] = __ldg(grow + 2 * H + row1);
        }

        float hk[16];
        if (t == 0) {
            #pragma unroll
            for (int i = 0; i < 16; i++) hk[i] = 0.f;
        } else {
            if (w == 0) {
                // throttled spin: one poll, then nanosleep backoff
                const int* tp = tagline + lane;
                int v = ld_acquire(tp);
                while (v < t) {
                    __nanosleep(40);
                    v = ld_acquire(tp);
                }
                // single L2 read of h, stage to smem + own registers
                const float4* hp = (const float4*)(hbank + (size_t)((t - 1) & 1) * H + lane * 16);
                float4 a0 = __ldcg(hp + 0);
                float4 a1 = __ldcg(hp + 1);
                float4 a2 = __ldcg(hp + 2);
                float4 a3 = __ldcg(hp + 3);
                float4* hs4 = (float4*)(hsh + lane * 16);
                hs4[0] = a0; hs4[1] = a1; hs4[2] = a2; hs4[3] = a3;
                hk[0]  = a0.x; hk[1]  = a0.y; hk[2]  = a0.z; hk[3]  = a0.w;
                hk[4]  = a1.x; hk[5]  = a1.y; hk[6]  = a1.z; hk[7]  = a1.w;
                hk[8]  = a2.x; hk[9]  = a2.y; hk[10] = a2.z; hk[11] = a2.w;
                hk[12] = a3.x; hk[13] = a3.y; hk[14] = a3.z; hk[15] = a3.w;
            }
            __syncthreads();   // barrier 1: hsh valid
            if (w != 0) {
                const float4* hs4 = (const float4*)(hsh + lane * 16);
                float4 a0 = hs4[0], a1 = hs4[1], a2 = hs4[2], a3 = hs4[3];
                hk[0]  = a0.x; hk[1]  = a0.y; hk[2]  = a0.z; hk[3]  = a0.w;
                hk[4]  = a1.x; hk[5]  = a1.y; hk[6]  = a1.z; hk[7]  = a1.w;
                hk[8]  = a2.x; hk[9]  = a2.y; hk[10] = a2.z; hk[11] = a2.w;
                hk[12] = a3.x; hk[13] = a3.y; hk[14] = a3.z; hk[15] = a3.w;
            }
        }

        // 6 dot products from register weights
        float dots[6];
        #pragma unroll
        for (int jj = 0; jj < 2; jj++)
            #pragma unroll
            for (int g = 0; g < 3; g++) {
                float acc = 0.f;
                #pragma unroll
                for (int i = 0; i < 16; i++)
                    acc = fmaf(wreg[jj][g][i], hk[i], acc);
                dots[jj * 3 + g] = acc;
            }
        // butterfly reduce all 6 across 32 lanes
        #pragma unroll
        for (int off = 16; off > 0; off >>= 1) {
            #pragma unroll
            for (int i = 0; i < 6; i++)
                dots[i] += __shfl_xor_sync(0xFFFFFFFFu, dots[i], off);
        }

        // lane0: gate math for both rows -> smem stage
        if (lane == 0) {
            float r0g = fsigmoid(g6[0] + dots[0] + br0);
            float z0g = fsigmoid(g6[1] + dots[1] + bz0);
            float n0g = ftanh(g6[2] + r0g * (dots[2] + bn0));
            float h0n = (1.f - z0g) * n0g + z0g * hr0;
            hr0 = h0n;

            float r1g = fsigmoid(g6[3] + dots[3] + br1);
            float z1g = fsigmoid(g6[4] + dots[4] + bz1);
            float n1g = ftanh(g6[5] + r1g * (dots[5] + bn1));
            float h1n = (1.f - z1g) * n1g + z1g * hr1;
            hr1 = h1n;

            hstage[w]     = h0n;
            hstage[w + 8] = h1n;
            if (t == S - 1) {
                g_hfinal[d * H + row0] = h0n;
                g_hfinal[d * H + row1] = h1n;
            }
        }
        __syncthreads();   // barrier 2: hstage complete (also protects hsh reuse)

        // tid0: publish 64B of h data + release the tag (plain stores, no RMW)
        if (tid == 0) {
            const float4* hs = (const float4*)hstage;
            float4 v0 = hs[0], v1 = hs[1], v2 = hs[2], v3 = hs[3];
            float4* hout = (float4*)(hbank + (size_t)(t & 1) * H + hbase);
            __stcg(hout + 0, v0);
            __stcg(hout + 1, v1);
            __stcg(hout + 2, v2);
            __stcg(hout + 3, v3);
            st_release(tagline + b, t + 1);   // orders the 4 data stores
        }
    }
}

// ---------------- dense1: h1 = relu(d1_w @ rep + d1_b) ----------------
__global__ void __launch_bounds__(256) k_dense1(const float* __restrict__ d1w,
                                                const float* __restrict__ d1b) {
    int warp = threadIdx.x >> 5, lane = threadIdx.x & 31;
    int row = blockIdx.x * 8 + warp;          // grid 128 -> 1024 rows
    const float* wr = d1w + (size_t)row * R4;
    float acc = 0.f;
    #pragma unroll 8
    for (int k = lane; k < R4; k += 32)
        acc = fmaf(wr[k], g_hfinal[k], acc);
    #pragma unroll
    for (int off = 16; off > 0; off >>= 1)
        acc += __shfl_xor_sync(0xFFFFFFFFu, acc, off);
    if (lane == 0) g_h1[row] = fmaxf(acc + d1b[row], 0.f);
}

// ---------------- dense2: out = sigmoid(d2_w . h1 + d2_b) ----------------
__global__ void __launch_bounds__(1024) k_dense2(const float* __restrict__ d2w,
                                                 const float* __restrict__ d2b,
                                                 float* __restrict__ out) {
    __shared__ float red[32];
    int tid = threadIdx.x, lane = tid & 31;
    float v = g_h1[tid] * d2w[tid];
    #pragma unroll
    for (int off = 16; off > 0; off >>= 1)
        v += __shfl_xor_sync(0xFFFFFFFFu, v, off);
    if (lane == 0) red[tid >> 5] = v;
    __syncthreads();
    if (tid < 32) {
        float s = red[tid];
        #pragma unroll
        for (int off = 16; off > 0; off >>= 1)
            s += __shfl_xor_sync(0xFFFFFFFFu, s, off);
        if (tid == 0) out[0] = 1.f / (1.f + expf(-(s + d2b[0])));
    }
}

// ---------------- launch ----------------
extern "C" void kernel_launch(void* const* d_in, const int* in_sizes, int n_in,
                              void* d_out, int out_size) {
    const void*  sent = d_in[0];
    const float* emb  = (const float*)d_in[1];

    GemmArgs ga; ScanArgs sa;
    for (int d = 0; d < 4; d++) {
        ga.Wih[d] = (const float*)d_in[2 + 4 * d + 0];
        sa.Whh[d] = (const float*)d_in[2 + 4 * d + 1];
        ga.bih[d] = (const float*)d_in[2 + 4 * d + 2];
        sa.bhh[d] = (const float*)d_in[2 + 4 * d + 3];
    }
    const float* d1w = (const float*)d_in[18];
    const float* d1b = (const float*)d_in[19];
    const float* d2w = (const float*)d_in[20];
    const float* d2b = (const float*)d_in[21];
    float* out = (float*)d_out;

    k_reset<<<1, 128>>>();
    k_gather<<<S, 128>>>(sent, emb);
    k_gemm_gi<<<dim3(S / BM, G3 / BN, NDIR), 256>>>(ga);
    k_scan<<<NDIR * BPD, NTH>>>(sa);
    k_dense1<<<D1 / 8, 256>>>(d1w, d1b);
    k_dense2<<<1, 1024>>>(d2w, d2b, out);
}